// round 10
// baseline (speedup 1.0000x reference)
#include <cuda_runtime.h>
#include <math.h>

// Problem constants
#define NN 16384
#define NB 64
#define NVOCAB 100
#define NL0 128
#define NH 64

// Scratch (__device__ globals — no allocation allowed)
__device__ float g_px[NN], g_py[NN], g_pz[NN], g_sq[NN];
__device__ int   g_start[NB + 1];     // segment starts: batch value v begins at g_start[v]
__device__ float g_table[NVOCAB];

// ---------------------------------------------------------------------------
// Kernel A: fused prep + MLP table.
//   blocks [0, 64):    prep — SoA pos split + sq, and O(1) segment-boundary
//                      detect on the sorted batch array (replaces the old
//                      per-node binary searches: 28 dependent loads -> 2
//                      independent loads per thread).
//   blocks [64, 164):  MLP collapsed to a 100-entry vocab table.
// batch dtype (int32 vs int64) auto-detected: int64 LE layout has word
// [NN-1] == 0 (a high word); int32 layout has it == max batch (~63).
// ---------------------------------------------------------------------------
__global__ void fused_prep_mlp(const void* __restrict__ batch_raw,
                               const float* __restrict__ pos,
                               const float* __restrict__ emb,
                               const float* __restrict__ w1,
                               const float* __restrict__ b1,
                               const float* __restrict__ w2,
                               const float* __restrict__ b2) {
    if (blockIdx.x < 64) {
        // ---- prep ----
        int i = blockIdx.x * 256 + threadIdx.x;

        float x = pos[3 * i + 0];
        float y = pos[3 * i + 1];
        float z = pos[3 * i + 2];
        g_px[i] = x; g_py[i] = y; g_pz[i] = z;
        // sq: separate rounds, no fma contraction (matches XLA mul+add)
        g_sq[i] = __fadd_rn(__fadd_rn(__fmul_rn(x, x), __fmul_rn(y, y)),
                            __fmul_rn(z, z));

        const int* w32 = (const int*)batch_raw;
        bool is32 = (w32[NN - 1] != 0);
        const long long* w64 = (const long long*)batch_raw;

        int bi = is32 ? w32[i] : (int)w64[i];

        // Segment-boundary scatter. Sorted batch => boundaries where the
        // value changes. Cover every v in [0, NB] exactly once (missing
        // values get empty segments), fully deterministic:
        //   thread 0:        g_start[v] = 0   for v in [0, b_0]
        //   batch change:    g_start[v] = i   for v in (b_{i-1}, b_i]
        //   thread NN-1:     g_start[v] = NN  for v in (b_{NN-1}, NB]
        if (i == 0) {
            for (int v = 0; v <= bi; v++) g_start[v] = 0;
        } else {
            int bp = is32 ? w32[i - 1] : (int)w64[i - 1];
            if (bp != bi)
                for (int v = bp + 1; v <= bi; v++) g_start[v] = i;
        }
        if (i == NN - 1) {
            for (int v = bi + 1; v <= NB; v++) g_start[v] = NN;
        }
    } else {
        // ---- MLP table: out depends on z only through emb[z]; 100 rows ----
        __shared__ float sh[NH];
        int v = blockIdx.x - 64;
        int j = threadIdx.x;

        if (j < NH) {
            const float* e = emb + (size_t)v * NL0;
            float acc = b1[j];
#pragma unroll 8
            for (int k = 0; k < NL0; k++)
                acc = fmaf(e[k], w1[k * NH + j], acc);
            // silu(x) = x * sigmoid(x)
            float s = 1.0f / (1.0f + expf(-acc));
            sh[j] = (acc * s) * w2[j];
        }
        __syncthreads();
        if (j == 0) {
            float o = 0.0f;
            for (int k = 0; k < NH; k++) o += sh[k];
            g_table[v] = o + b2[0];
        }
    }
}

// ---------------------------------------------------------------------------
// Kernel B: adjacency mask (HBM-write bound) + gather epilogue.
//   blocks [0, 64) additionally write out[i] = table[z[i]] first.
//
// Mapping: block b -> row (b >> 1), half (b & 1). Each block covers 2048
// float4 chunks (half a row); thread handles chunks tid + k*256, k=0..7
// (lane-contiguous per store instruction -> full coalescing). Row band:
//   b  = batch[row];  lo = g_start[b];  hi = g_start[b+1]
// (all uniform, L2-hot). Blocks with no band overlap take a pure 8x STG
// zero loop with zero per-iteration ALU.
//
// __stcs (evict-first streaming) is MANDATORY: A/B'd at wall-clock, plain
// stores cost +26us (180.8 vs 154.3). ncu single-pass DRAM% said the
// opposite — trust graph-replay wall time, not single-replay ncu, here.
//
// In-band: d2 = (sq_i + sq_j) - 2*dot (ascending fma chain) — exact match
// of the reference's sq[:,None]+sq[None,:]-2*(pos@pos.T) rounding.
// ---------------------------------------------------------------------------
__global__ void adj_gather_kernel(const void* __restrict__ batch_raw,
                                  const int* __restrict__ z,
                                  float* __restrict__ out,
                                  float4* __restrict__ adj) {
    if (blockIdx.x < 64) {
        int idx = blockIdx.x * 256 + threadIdx.x;
        out[idx] = g_table[z[idx]];
    }

    int row  = blockIdx.x >> 1;
    int half = blockIdx.x & 1;

    const int* w32 = (const int*)batch_raw;
    bool is32 = (w32[NN - 1] != 0);
    int b = is32 ? w32[row] : (int)((const long long*)batch_raw)[row];
    int lo = g_start[b];
    int hi = g_start[b + 1];

    unsigned cbase = (unsigned)row * 4096u + (unsigned)half * 2048u; // chunk base
    int jbase = half * 8192;                                        // element base

    const float4 zero = make_float4(0.f, 0.f, 0.f, 0.f);

    // No overlap between this half-row [jbase, jbase+8192) and [lo, hi)?
    if (jbase + 8192 <= lo || jbase >= hi) {
        // Pure zero-fill fast path
#pragma unroll
        for (int k = 0; k < 8; k++)
            __stcs(&adj[cbase + threadIdx.x + k * 256], zero);
    } else {
        float xi = g_px[row], yi = g_py[row], zi = g_pz[row], sqi = g_sq[row];
#pragma unroll
        for (int k = 0; k < 8; k++) {
            int c  = threadIdx.x + k * 256;      // chunk within half-row
            int j0 = jbase + (c << 2);           // first element of chunk
            float4 v = zero;
            if (j0 + 3 >= lo && j0 < hi) {
                float r[4];
#pragma unroll
                for (int e = 0; e < 4; e++) {
                    int j = j0 + e;
                    float val = 0.0f;
                    if (j >= lo && j < hi && j != row) {
                        float dot = fmaf(zi, g_pz[j],
                                    fmaf(yi, g_py[j],
                                         __fmul_rn(xi, g_px[j])));
                        float d2 = __fsub_rn(__fadd_rn(sqi, g_sq[j]),
                                             __fmul_rn(2.0f, dot));
                        val = (d2 < 64.0f) ? 1.0f : 0.0f;
                    }
                    r[e] = val;
                }
                v = make_float4(r[0], r[1], r[2], r[3]);
            }
            __stcs(&adj[cbase + c], v);
        }
    }
}

// ---------------------------------------------------------------------------
extern "C" void kernel_launch(void* const* d_in, const int* in_sizes, int n_in,
                              void* d_out, int out_size) {
    const int*   z     = (const int*)d_in[0];
    const void*  batch = d_in[1];           // int32 or int64, device-detected
    const float* pos   = (const float*)d_in[2];
    const float* emb   = (const float*)d_in[3];
    const float* w1    = (const float*)d_in[4];
    const float* b1    = (const float*)d_in[5];
    const float* w2    = (const float*)d_in[6];
    const float* b2    = (const float*)d_in[7];
    float* out = (float*)d_out;

    fused_prep_mlp<<<164, 256>>>(batch, pos, emb, w1, b1, w2, b2);
    adj_gather_kernel<<<32768, 256>>>(batch, z, out, (float4*)(out + NN));
}